// round 2
// baseline (speedup 1.0000x reference)
#include <cuda_runtime.h>

#define BB 4
#define NQ 2048
#define NK 2048
#define DD 512
#define HH 8
#define DH 64
#define M_ROWS (BB * NQ)          // 8192
#define O_ELEMS (BB * NQ * DD)    // 4194304
#define A_ELEMS ((size_t)HH * BB * NQ * NK) // 134217728

// ---------------- scratch (static device globals; no allocs) ----------------
__device__ float g_Qp[O_ELEMS];
__device__ float g_Kp[O_ELEMS];
__device__ float g_Vp[O_ELEMS];
__device__ float g_O1[O_ELEMS];
__device__ float g_X [O_ELEMS];

// ---------------- fast exp: exp2-split, pure FMA (avoids MUFU wall) --------
__device__ __forceinline__ float fast_exp(float x) {
    x = fmaxf(x, -87.0f);
    float y = x * 1.4426950408889634f;
    float n = rintf(y);
    float f = y - n;
    float p =          1.53958946e-4f;
    p = fmaf(p, f, 1.33335581e-3f);
    p = fmaf(p, f, 9.61812911e-3f);
    p = fmaf(p, f, 5.55041087e-2f);
    p = fmaf(p, f, 2.40226507e-1f);
    p = fmaf(p, f, 6.93147181e-1f);
    p = fmaf(p, f, 1.0f);
    int ni = (int)n;
    return __int_as_float((ni + 127) << 23) * p;
}

// ---------------- GEMM: C[M,512] = A[M,512] @ W[512,512] + b ---------------
// BM=128, BN=64, BK=16, 256 threads, 8x4 per thread.
// RELURES: C = A + relu(A@W + b)   (for the Wo stage)
template <bool RELURES>
__global__ void __launch_bounds__(256) gemm512(const float* __restrict__ A,
                                               const float* __restrict__ W,
                                               const float* __restrict__ bias,
                                               float* __restrict__ C) {
    __shared__ float As[16][132];   // transposed [k][m], 132 keeps float4 align
    __shared__ float Bs[16][64];
    const int bm = blockIdx.y * 128, bn = blockIdx.x * 64;
    const int tid = threadIdx.x;
    const int tx = tid & 15, ty = tid >> 4;
    const int lr = tid >> 2, lc = (tid & 3) * 4;   // A-tile loader
    const int wr = tid >> 4, wc = (tid & 15) * 4;  // W-tile loader

    float acc[8][4];
#pragma unroll
    for (int i = 0; i < 8; i++)
#pragma unroll
        for (int j = 0; j < 4; j++) acc[i][j] = 0.f;

    for (int kt = 0; kt < 512; kt += 16) {
        float4 a0 = *(const float4*)(A + (size_t)(bm + lr)      * 512 + kt + lc);
        float4 a1 = *(const float4*)(A + (size_t)(bm + lr + 64) * 512 + kt + lc);
        float4 w0 = *(const float4*)(W + (size_t)(kt + wr) * 512 + bn + wc);
        __syncthreads();
        As[lc + 0][lr] = a0.x; As[lc + 1][lr] = a0.y;
        As[lc + 2][lr] = a0.z; As[lc + 3][lr] = a0.w;
        As[lc + 0][lr + 64] = a1.x; As[lc + 1][lr + 64] = a1.y;
        As[lc + 2][lr + 64] = a1.z; As[lc + 3][lr + 64] = a1.w;
        *(float4*)&Bs[wr][wc] = w0;
        __syncthreads();
#pragma unroll
        for (int kk = 0; kk < 16; kk++) {
            float4 av0 = *(const float4*)&As[kk][ty * 8];
            float4 av1 = *(const float4*)&As[kk][ty * 8 + 4];
            float4 bv  = *(const float4*)&Bs[kk][tx * 4];
            float aa[8] = {av0.x, av0.y, av0.z, av0.w, av1.x, av1.y, av1.z, av1.w};
            float bb[4] = {bv.x, bv.y, bv.z, bv.w};
#pragma unroll
            for (int i = 0; i < 8; i++)
#pragma unroll
                for (int j = 0; j < 4; j++)
                    acc[i][j] = fmaf(aa[i], bb[j], acc[i][j]);
        }
    }
    float4 bb = *(const float4*)(bias + bn + tx * 4);
#pragma unroll
    for (int i = 0; i < 8; i++) {
        size_t ro = (size_t)(bm + ty * 8 + i) * 512 + bn + tx * 4;
        float4 o;
        o.x = acc[i][0] + bb.x; o.y = acc[i][1] + bb.y;
        o.z = acc[i][2] + bb.z; o.w = acc[i][3] + bb.w;
        if (RELURES) {
            float4 x = *(const float4*)(A + ro);
            o.x = x.x + fmaxf(o.x, 0.f);
            o.y = x.y + fmaxf(o.y, 0.f);
            o.z = x.z + fmaxf(o.z, 0.f);
            o.w = x.w + fmaxf(o.w, 0.f);
        }
        *(float4*)(C + ro) = o;
    }
}

// ---------------- fused K/V projection: shares the A (=K input) tile -------
__global__ void __launch_bounds__(256) gemm512_kv(const float* __restrict__ A,
                                                  const float* __restrict__ Wk,
                                                  const float* __restrict__ bk,
                                                  const float* __restrict__ Wv,
                                                  const float* __restrict__ bv,
                                                  float* __restrict__ Ck,
                                                  float* __restrict__ Cv) {
    __shared__ float As[16][132];
    __shared__ float Bk[16][64];
    __shared__ float Bv[16][64];
    const int bm = blockIdx.y * 128, bn = blockIdx.x * 64;
    const int tid = threadIdx.x;
    const int tx = tid & 15, ty = tid >> 4;
    const int lr = tid >> 2, lc = (tid & 3) * 4;
    const int wr = tid >> 4, wc = (tid & 15) * 4;

    float ak[8][4], av[8][4];
#pragma unroll
    for (int i = 0; i < 8; i++)
#pragma unroll
        for (int j = 0; j < 4; j++) { ak[i][j] = 0.f; av[i][j] = 0.f; }

    for (int kt = 0; kt < 512; kt += 16) {
        float4 a0 = *(const float4*)(A + (size_t)(bm + lr)      * 512 + kt + lc);
        float4 a1 = *(const float4*)(A + (size_t)(bm + lr + 64) * 512 + kt + lc);
        float4 wk0 = *(const float4*)(Wk + (size_t)(kt + wr) * 512 + bn + wc);
        float4 wv0 = *(const float4*)(Wv + (size_t)(kt + wr) * 512 + bn + wc);
        __syncthreads();
        As[lc + 0][lr] = a0.x; As[lc + 1][lr] = a0.y;
        As[lc + 2][lr] = a0.z; As[lc + 3][lr] = a0.w;
        As[lc + 0][lr + 64] = a1.x; As[lc + 1][lr + 64] = a1.y;
        As[lc + 2][lr + 64] = a1.z; As[lc + 3][lr + 64] = a1.w;
        *(float4*)&Bk[wr][wc] = wk0;
        *(float4*)&Bv[wr][wc] = wv0;
        __syncthreads();
#pragma unroll
        for (int kk = 0; kk < 16; kk++) {
            float4 a0v = *(const float4*)&As[kk][ty * 8];
            float4 a1v = *(const float4*)&As[kk][ty * 8 + 4];
            float4 bkv = *(const float4*)&Bk[kk][tx * 4];
            float4 bvv = *(const float4*)&Bv[kk][tx * 4];
            float aa[8] = {a0v.x, a0v.y, a0v.z, a0v.w, a1v.x, a1v.y, a1v.z, a1v.w};
            float kb[4] = {bkv.x, bkv.y, bkv.z, bkv.w};
            float vb[4] = {bvv.x, bvv.y, bvv.z, bvv.w};
#pragma unroll
            for (int i = 0; i < 8; i++)
#pragma unroll
                for (int j = 0; j < 4; j++) {
                    ak[i][j] = fmaf(aa[i], kb[j], ak[i][j]);
                    av[i][j] = fmaf(aa[i], vb[j], av[i][j]);
                }
        }
    }
    float4 kb = *(const float4*)(bk + bn + tx * 4);
    float4 vb = *(const float4*)(bv + bn + tx * 4);
#pragma unroll
    for (int i = 0; i < 8; i++) {
        size_t ro = (size_t)(bm + ty * 8 + i) * 512 + bn + tx * 4;
        float4 ok, ov;
        ok.x = ak[i][0] + kb.x; ok.y = ak[i][1] + kb.y;
        ok.z = ak[i][2] + kb.z; ok.w = ak[i][3] + kb.w;
        ov.x = av[i][0] + vb.x; ov.y = av[i][1] + vb.y;
        ov.z = av[i][2] + vb.z; ov.w = av[i][3] + vb.w;
        *(float4*)(Ck + ro) = ok;
        *(float4*)(Cv + ro) = ov;
    }
}

// ---------------- attention: S=QK^T, softmax (writes A), O=Q+AV ------------
#define TQ 16
#define KT 256
#define SP 2052   // Ss row stride (float4-aligned, q-rows hit distinct banks)
#define QP 68
#define KP 68
#define ATTN_SMEM_FLOATS (TQ * SP + TQ * QP + KT * KP + 4 * TQ * 64)
#define ATTN_SMEM_BYTES  (ATTN_SMEM_FLOATS * 4)

__global__ void __launch_bounds__(256, 1) attn_kernel(
    const float* __restrict__ Qp, const float* __restrict__ Kp,
    const float* __restrict__ Vp, float* __restrict__ Aout,
    float* __restrict__ O1) {
    const int q0 = blockIdx.x * TQ;
    const int b  = blockIdx.y;
    const int h  = blockIdx.z;
    extern __shared__ float sm[];
    float* Ss = sm;                   // [TQ][SP]
    float* Qs = Ss + TQ * SP;         // [TQ][QP]
    float* KV = Qs + TQ * QP;         // [KT][KP]  (K tile, then V tile)
    float* Op = KV + KT * KP;         // [4][TQ][64] partial O
    const int tid = threadIdx.x;
    const int hbase = h * DH;

    // stage Q tile (also used for residual at the end)
    {
        int r = tid >> 4, c = (tid & 15) * 4;
        float4 v = *(const float4*)(Qp + (size_t)(b * NQ + q0 + r) * DD + hbase + c);
        *(float4*)(Qs + r * QP + c) = v;
    }
    __syncthreads();

    // ---- S phase: thread owns 4 q-rows x 4 k-cols (k strided by 64) ----
    const int kg = tid & 63;
    const int qg = tid >> 6;
    const float scale = 0.04419417382415922f;  // 1/sqrt(512)
    for (int kp = 0; kp < NK; kp += KT) {
        __syncthreads();
        {
            int rr = tid >> 4, c = (tid & 15) * 4;
#pragma unroll
            for (int it = 0; it < KT / 16; it++) {
                int k = it * 16 + rr;
                float4 v = *(const float4*)(Kp + (size_t)(b * NK + kp + k) * DD + hbase + c);
                *(float4*)(KV + k * KP + c) = v;
            }
        }
        __syncthreads();
        float acc[4][4];
#pragma unroll
        for (int j = 0; j < 4; j++)
#pragma unroll
            for (int i = 0; i < 4; i++) acc[j][i] = 0.f;
#pragma unroll
        for (int d4 = 0; d4 < DH; d4 += 4) {
            float4 qv[4], kv[4];
#pragma unroll
            for (int j = 0; j < 4; j++)
                qv[j] = *(const float4*)(Qs + (qg * 4 + j) * QP + d4);
#pragma unroll
            for (int i = 0; i < 4; i++)
                kv[i] = *(const float4*)(KV + (kg + i * 64) * KP + d4);
#pragma unroll
            for (int j = 0; j < 4; j++)
#pragma unroll
                for (int i = 0; i < 4; i++) {
                    acc[j][i] = fmaf(qv[j].x, kv[i].x, acc[j][i]);
                    acc[j][i] = fmaf(qv[j].y, kv[i].y, acc[j][i]);
                    acc[j][i] = fmaf(qv[j].z, kv[i].z, acc[j][i]);
                    acc[j][i] = fmaf(qv[j].w, kv[i].w, acc[j][i]);
                }
        }
#pragma unroll
        for (int j = 0; j < 4; j++)
#pragma unroll
            for (int i = 0; i < 4; i++)
                Ss[(qg * 4 + j) * SP + kp + kg + i * 64] = acc[j][i] * scale;
    }
    __syncthreads();

    // ---- softmax per row (warp handles 2 rows), write A (streaming) ----
    {
        const int warp = tid >> 5, lane = tid & 31;
#pragma unroll
        for (int rr = 0; rr < 2; rr++) {
            int r = warp * 2 + rr;
            float* row = Ss + r * SP;
            float m = -1e30f;
#pragma unroll 4
            for (int k = lane * 4; k < NK; k += 128) {
                float4 v = *(const float4*)(row + k);
                m = fmaxf(m, fmaxf(fmaxf(v.x, v.y), fmaxf(v.z, v.w)));
            }
#pragma unroll
            for (int o = 16; o; o >>= 1) m = fmaxf(m, __shfl_xor_sync(0xffffffffu, m, o));
            float s = 0.f;
#pragma unroll 4
            for (int k = lane * 4; k < NK; k += 128) {
                float4 v = *(const float4*)(row + k);
                v.x = fast_exp(v.x - m); v.y = fast_exp(v.y - m);
                v.z = fast_exp(v.z - m); v.w = fast_exp(v.w - m);
                s += (v.x + v.y) + (v.z + v.w);
                *(float4*)(row + k) = v;
            }
#pragma unroll
            for (int o = 16; o; o >>= 1) s += __shfl_xor_sync(0xffffffffu, s, o);
            float inv = 1.0f / s;
            float* arow = Aout + (size_t)((h * BB + b) * NQ + q0 + r) * NK;
#pragma unroll 4
            for (int k = lane * 4; k < NK; k += 128) {
                float4 v = *(const float4*)(row + k);
                v.x *= inv; v.y *= inv; v.z *= inv; v.w *= inv;
                *(float4*)(row + k) = v;         // normalized, reused by AV
                __stcs((float4*)(arow + k), v);  // streaming A output, keep L2 clean
            }
        }
    }

    // ---- AV phase: thread owns 4 q x 4 d, 4 k-phases reduced via Op ----
    {
        const int tile = tid & 63, phase = tid >> 6;
        const int dg = (tile & 15) * 4, qg2 = (tile >> 4) * 4;
        float oacc[4][4];
#pragma unroll
        for (int j = 0; j < 4; j++)
#pragma unroll
            for (int i = 0; i < 4; i++) oacc[j][i] = 0.f;
        for (int kp = 0; kp < NK; kp += KT) {
            __syncthreads();
            {
                int rr = tid >> 4, c = (tid & 15) * 4;
#pragma unroll
                for (int it = 0; it < KT / 16; it++) {
                    int k = it * 16 + rr;
                    float4 v = *(const float4*)(Vp + (size_t)(b * NK + kp + k) * DD + hbase + c);
                    *(float4*)(KV + k * KP + c) = v;
                }
            }
            __syncthreads();
#pragma unroll 4
            for (int kk = phase; kk < KT; kk += 4) {
                float4 vv = *(const float4*)(KV + kk * KP + dg);
                float a0 = Ss[(qg2 + 0) * SP + kp + kk];
                float a1 = Ss[(qg2 + 1) * SP + kp + kk];
                float a2 = Ss[(qg2 + 2) * SP + kp + kk];
                float a3 = Ss[(qg2 + 3) * SP + kp + kk];
                oacc[0][0] = fmaf(a0, vv.x, oacc[0][0]);
                oacc[0][1] = fmaf(a0, vv.y, oacc[0][1]);
                oacc[0][2] = fmaf(a0, vv.z, oacc[0][2]);
                oacc[0][3] = fmaf(a0, vv.w, oacc[0][3]);
                oacc[1][0] = fmaf(a1, vv.x, oacc[1][0]);
                oacc[1][1] = fmaf(a1, vv.y, oacc[1][1]);
                oacc[1][2] = fmaf(a1, vv.z, oacc[1][2]);
                oacc[1][3] = fmaf(a1, vv.w, oacc[1][3]);
                oacc[2][0] = fmaf(a2, vv.x, oacc[2][0]);
                oacc[2][1] = fmaf(a2, vv.y, oacc[2][1]);
                oacc[2][2] = fmaf(a2, vv.z, oacc[2][2]);
                oacc[2][3] = fmaf(a2, vv.w, oacc[2][3]);
                oacc[3][0] = fmaf(a3, vv.x, oacc[3][0]);
                oacc[3][1] = fmaf(a3, vv.y, oacc[3][1]);
                oacc[3][2] = fmaf(a3, vv.z, oacc[3][2]);
                oacc[3][3] = fmaf(a3, vv.w, oacc[3][3]);
            }
        }
#pragma unroll
        for (int j = 0; j < 4; j++)
            *(float4*)(Op + (phase * TQ + qg2 + j) * 64 + dg) =
                make_float4(oacc[j][0], oacc[j][1], oacc[j][2], oacc[j][3]);
    }
    __syncthreads();
    // reduce 4 k-phases, add Q residual, write O1
    for (int idx = tid; idx < TQ * 64; idx += 256) {
        int q = idx >> 6, dd = idx & 63;
        float o = Op[(0 * TQ + q) * 64 + dd] + Op[(1 * TQ + q) * 64 + dd]
                + Op[(2 * TQ + q) * 64 + dd] + Op[(3 * TQ + q) * 64 + dd];
        o += Qs[q * QP + dd];
        O1[(size_t)(b * NQ + q0 + q) * DD + hbase + dd] = o;
    }
}

// ---------------- layernorm over last dim (512), warp per row --------------
__global__ void __launch_bounds__(256) ln_kernel(const float* __restrict__ X,
                                                 const float* __restrict__ g,
                                                 const float* __restrict__ bt,
                                                 float* __restrict__ Y) {
    int row = blockIdx.x * 8 + (threadIdx.x >> 5);
    int lane = threadIdx.x & 31;
    const float* x = X + (size_t)row * 512;
    float4 v[4];
    float s = 0.f, s2 = 0.f;
#pragma unroll
    for (int i = 0; i < 4; i++) {
        v[i] = *(const float4*)(x + lane * 4 + i * 128);
        s  += (v[i].x + v[i].y) + (v[i].z + v[i].w);
        s2 += (v[i].x * v[i].x + v[i].y * v[i].y) + (v[i].z * v[i].z + v[i].w * v[i].w);
    }
#pragma unroll
    for (int o = 16; o; o >>= 1) {
        s  += __shfl_xor_sync(0xffffffffu, s,  o);
        s2 += __shfl_xor_sync(0xffffffffu, s2, o);
    }
    float m   = s * (1.f / 512.f);
    float var = s2 * (1.f / 512.f) - m * m;
    float r   = rsqrtf(var + 1e-5f);
#pragma unroll
    for (int i = 0; i < 4; i++) {
        int c = lane * 4 + i * 128;
        float4 gg = *(const float4*)(g + c);
        float4 bb = *(const float4*)(bt + c);
        float4 o;
        o.x = (v[i].x - m) * r * gg.x + bb.x;
        o.y = (v[i].y - m) * r * gg.y + bb.y;
        o.z = (v[i].z - m) * r * gg.z + bb.z;
        o.w = (v[i].w - m) * r * gg.w + bb.w;
        *(float4*)(Y + (size_t)row * 512 + c) = o;
    }
}

// ---------------------------- launcher -------------------------------------
extern "C" void kernel_launch(void* const* d_in, const int* in_sizes, int n_in,
                              void* d_out, int out_size) {
    const float* Q  = (const float*)d_in[0];
    const float* K  = (const float*)d_in[1];
    const float* Wq = (const float*)d_in[2];
    const float* bq = (const float*)d_in[3];
    const float* Wk = (const float*)d_in[4];
    const float* bk = (const float*)d_in[5];
    const float* Wv = (const float*)d_in[6];
    const float* bv = (const float*)d_in[7];
    const float* Wo = (const float*)d_in[8];
    const float* bo = (const float*)d_in[9];
    const float* g0 = (const float*)d_in[10];
    const float* b0 = (const float*)d_in[11];
    const float* g1 = (const float*)d_in[12];
    const float* b1 = (const float*)d_in[13];

    float* out = (float*)d_out;
    float* Aout = out + ((size_t)out_size - A_ELEMS);  // O first, A second

    float *Qp, *Kp, *Vp, *O1, *X;
    cudaGetSymbolAddress((void**)&Qp, g_Qp);
    cudaGetSymbolAddress((void**)&Kp, g_Kp);
    cudaGetSymbolAddress((void**)&Vp, g_Vp);
    cudaGetSymbolAddress((void**)&O1, g_O1);
    cudaGetSymbolAddress((void**)&X,  g_X);

    cudaFuncSetAttribute(attn_kernel, cudaFuncAttributeMaxDynamicSharedMemorySize,
                         ATTN_SMEM_BYTES);

    dim3 gg(512 / 64, M_ROWS / 128);
    gemm512<false><<<gg, 256>>>(Q, Wq, bq, Qp);
    gemm512_kv<<<gg, 256>>>(K, Wk, bk, Wv, bv, Kp, Vp);

    attn_kernel<<<dim3(NQ / TQ, BB, HH), 256, ATTN_SMEM_BYTES>>>(Qp, Kp, Vp, Aout, O1);

    ln_kernel<<<M_ROWS / 8, 256>>>(O1, g0, b0, X);
    gemm512<true><<<gg, 256>>>(X, Wo, bo, O1);
    ln_kernel<<<M_ROWS / 8, 256>>>(O1, g1, b1, out);
}

// round 3
// speedup vs baseline: 1.3991x; 1.3991x over previous
#include <cuda_runtime.h>
#include <cstdint>

#define BB 4
#define NQ 2048
#define NK 2048
#define DD 512
#define HH 8
#define DH 64
#define M_ROWS (BB * NQ)          // 8192
#define O_ELEMS (BB * NQ * DD)    // 4194304
#define A_ELEMS ((size_t)HH * BB * NQ * NK) // 134217728

// ---------------- scratch (static device globals; no allocs) ----------------
__device__ float g_Qp[O_ELEMS];
__device__ float g_Kp[O_ELEMS];
__device__ float g_Vp[O_ELEMS];
__device__ float g_O1[O_ELEMS];
__device__ float g_X [O_ELEMS];

// ---------------- fast exp: exp2-split, pure FMA (avoids MUFU wall) --------
__device__ __forceinline__ float fast_exp(float x) {
    x = fmaxf(x, -87.0f);
    float y = x * 1.4426950408889634f;
    float n = rintf(y);
    float f = y - n;
    float p =          1.53958946e-4f;
    p = fmaf(p, f, 1.33335581e-3f);
    p = fmaf(p, f, 9.61812911e-3f);
    p = fmaf(p, f, 5.55041087e-2f);
    p = fmaf(p, f, 2.40226507e-1f);
    p = fmaf(p, f, 6.93147181e-1f);
    p = fmaf(p, f, 1.0f);
    int ni = (int)n;
    return __int_as_float((ni + 127) << 23) * p;
}

// ---------------- tf32 helpers ---------------------------------------------
__device__ __forceinline__ uint32_t f2tf32(float x) {
    uint32_t r;
    asm("cvt.rna.tf32.f32 %0, %1;" : "=r"(r) : "f"(x));
    return r;
}
__device__ __forceinline__ float f2tf32f(float x) {
    return __uint_as_float(f2tf32(x));
}
__device__ __forceinline__ void mma_tf32(float c[4],
                                         uint32_t a0, uint32_t a1,
                                         uint32_t a2, uint32_t a3,
                                         uint32_t b0, uint32_t b1) {
    asm volatile(
        "mma.sync.aligned.m16n8k8.row.col.f32.tf32.tf32.f32 "
        "{%0,%1,%2,%3},{%4,%5,%6,%7},{%8,%9},{%0,%1,%2,%3};\n"
        : "+f"(c[0]), "+f"(c[1]), "+f"(c[2]), "+f"(c[3])
        : "r"(a0), "r"(a1), "r"(a2), "r"(a3), "r"(b0), "r"(b1));
}

// ---------------- GEMM: C[M,512] = A[M,512] @ W[512,512] + b ---------------
template <bool RELURES>
__global__ void __launch_bounds__(256) gemm512(const float* __restrict__ A,
                                               const float* __restrict__ W,
                                               const float* __restrict__ bias,
                                               float* __restrict__ C) {
    __shared__ float As[16][132];   // transposed [k][m], 132 keeps float4 align
    __shared__ float Bs[16][64];
    const int bm = blockIdx.y * 128, bn = blockIdx.x * 64;
    const int tid = threadIdx.x;
    const int tx = tid & 15, ty = tid >> 4;
    const int lr = tid >> 2, lc = (tid & 3) * 4;   // A-tile loader
    const int wr = tid >> 4, wc = (tid & 15) * 4;  // W-tile loader

    float acc[8][4];
#pragma unroll
    for (int i = 0; i < 8; i++)
#pragma unroll
        for (int j = 0; j < 4; j++) acc[i][j] = 0.f;

    for (int kt = 0; kt < 512; kt += 16) {
        float4 a0 = *(const float4*)(A + (size_t)(bm + lr)      * 512 + kt + lc);
        float4 a1 = *(const float4*)(A + (size_t)(bm + lr + 64) * 512 + kt + lc);
        float4 w0 = *(const float4*)(W + (size_t)(kt + wr) * 512 + bn + wc);
        __syncthreads();
        As[lc + 0][lr] = a0.x; As[lc + 1][lr] = a0.y;
        As[lc + 2][lr] = a0.z; As[lc + 3][lr] = a0.w;
        As[lc + 0][lr + 64] = a1.x; As[lc + 1][lr + 64] = a1.y;
        As[lc + 2][lr + 64] = a1.z; As[lc + 3][lr + 64] = a1.w;
        *(float4*)&Bs[wr][wc] = w0;
        __syncthreads();
#pragma unroll
        for (int kk = 0; kk < 16; kk++) {
            float4 av0 = *(const float4*)&As[kk][ty * 8];
            float4 av1 = *(const float4*)&As[kk][ty * 8 + 4];
            float4 bv  = *(const float4*)&Bs[kk][tx * 4];
            float aa[8] = {av0.x, av0.y, av0.z, av0.w, av1.x, av1.y, av1.z, av1.w};
            float bb[4] = {bv.x, bv.y, bv.z, bv.w};
#pragma unroll
            for (int i = 0; i < 8; i++)
#pragma unroll
                for (int j = 0; j < 4; j++)
                    acc[i][j] = fmaf(aa[i], bb[j], acc[i][j]);
        }
    }
    float4 bb = *(const float4*)(bias + bn + tx * 4);
#pragma unroll
    for (int i = 0; i < 8; i++) {
        size_t ro = (size_t)(bm + ty * 8 + i) * 512 + bn + tx * 4;
        float4 o;
        o.x = acc[i][0] + bb.x; o.y = acc[i][1] + bb.y;
        o.z = acc[i][2] + bb.z; o.w = acc[i][3] + bb.w;
        if (RELURES) {
            float4 x = *(const float4*)(A + ro);
            o.x = x.x + fmaxf(o.x, 0.f);
            o.y = x.y + fmaxf(o.y, 0.f);
            o.z = x.z + fmaxf(o.z, 0.f);
            o.w = x.w + fmaxf(o.w, 0.f);
        }
        *(float4*)(C + ro) = o;
    }
}

// ---------------- fused K/V projection: shares the A (=K input) tile -------
__global__ void __launch_bounds__(256) gemm512_kv(const float* __restrict__ A,
                                                  const float* __restrict__ Wk,
                                                  const float* __restrict__ bk,
                                                  const float* __restrict__ Wv,
                                                  const float* __restrict__ bv,
                                                  float* __restrict__ Ck,
                                                  float* __restrict__ Cv) {
    __shared__ float As[16][132];
    __shared__ float Bk[16][64];
    __shared__ float Bv[16][64];
    const int bm = blockIdx.y * 128, bn = blockIdx.x * 64;
    const int tid = threadIdx.x;
    const int tx = tid & 15, ty = tid >> 4;
    const int lr = tid >> 2, lc = (tid & 3) * 4;
    const int wr = tid >> 4, wc = (tid & 15) * 4;

    float ak[8][4], av[8][4];
#pragma unroll
    for (int i = 0; i < 8; i++)
#pragma unroll
        for (int j = 0; j < 4; j++) { ak[i][j] = 0.f; av[i][j] = 0.f; }

    for (int kt = 0; kt < 512; kt += 16) {
        float4 a0 = *(const float4*)(A + (size_t)(bm + lr)      * 512 + kt + lc);
        float4 a1 = *(const float4*)(A + (size_t)(bm + lr + 64) * 512 + kt + lc);
        float4 wk0 = *(const float4*)(Wk + (size_t)(kt + wr) * 512 + bn + wc);
        float4 wv0 = *(const float4*)(Wv + (size_t)(kt + wr) * 512 + bn + wc);
        __syncthreads();
        As[lc + 0][lr] = a0.x; As[lc + 1][lr] = a0.y;
        As[lc + 2][lr] = a0.z; As[lc + 3][lr] = a0.w;
        As[lc + 0][lr + 64] = a1.x; As[lc + 1][lr + 64] = a1.y;
        As[lc + 2][lr + 64] = a1.z; As[lc + 3][lr + 64] = a1.w;
        *(float4*)&Bk[wr][wc] = wk0;
        *(float4*)&Bv[wr][wc] = wv0;
        __syncthreads();
#pragma unroll
        for (int kk = 0; kk < 16; kk++) {
            float4 a0v = *(const float4*)&As[kk][ty * 8];
            float4 a1v = *(const float4*)&As[kk][ty * 8 + 4];
            float4 bkv = *(const float4*)&Bk[kk][tx * 4];
            float4 bvv = *(const float4*)&Bv[kk][tx * 4];
            float aa[8] = {a0v.x, a0v.y, a0v.z, a0v.w, a1v.x, a1v.y, a1v.z, a1v.w};
            float kb[4] = {bkv.x, bkv.y, bkv.z, bkv.w};
            float vb[4] = {bvv.x, bvv.y, bvv.z, bvv.w};
#pragma unroll
            for (int i = 0; i < 8; i++)
#pragma unroll
                for (int j = 0; j < 4; j++) {
                    ak[i][j] = fmaf(aa[i], kb[j], ak[i][j]);
                    av[i][j] = fmaf(aa[i], vb[j], av[i][j]);
                }
        }
    }
    float4 kb = *(const float4*)(bk + bn + tx * 4);
    float4 vb = *(const float4*)(bv + bn + tx * 4);
#pragma unroll
    for (int i = 0; i < 8; i++) {
        size_t ro = (size_t)(bm + ty * 8 + i) * 512 + bn + tx * 4;
        float4 ok, ov;
        ok.x = ak[i][0] + kb.x; ok.y = ak[i][1] + kb.y;
        ok.z = ak[i][2] + kb.z; ok.w = ak[i][3] + kb.w;
        ov.x = av[i][0] + vb.x; ov.y = av[i][1] + vb.y;
        ov.z = av[i][2] + vb.z; ov.w = av[i][3] + vb.w;
        *(float4*)(Ck + ro) = ok;
        *(float4*)(Cv + ro) = ov;
    }
}

// ---------------- attention: S=QK^T ( tf32 mma ), softmax, O=Q+AV ----------
#define TQ 16
#define KT 256
#define SP 2052   // Ss row stride; %32==4 -> conflict-free mma A-frag reads
#define QP 68     // Qs row stride; %32==4 -> conflict-free Q fragment reads
#define KPK 68    // K tile stride  (S phase B-frag: tok stride 4 banks)
#define KPV 72    // V tile stride  (AV phase B-frag: tok stride 8 banks)
#define ATTN_SMEM_FLOATS (TQ * SP + TQ * QP + KT * KPV + 4 * TQ * 64)
#define ATTN_SMEM_BYTES  (ATTN_SMEM_FLOATS * 4)

__global__ void __launch_bounds__(256, 1) attn_kernel(
    const float* __restrict__ Qp, const float* __restrict__ Kp,
    const float* __restrict__ Vp, float* __restrict__ Aout,
    float* __restrict__ O1) {
    const int q0 = blockIdx.x * TQ;
    const int b  = blockIdx.y;
    const int h  = blockIdx.z;
    extern __shared__ float sm[];
    float* Ss = sm;                   // [TQ][SP]
    float* Qs = Ss + TQ * SP;         // [TQ][QP]   raw fp32 (residual + frags)
    float* KV = Qs + TQ * QP;         // [KT][KPV]  (K tile @KPK, V tile @KPV)
    float* Op = KV + KT * KPV;        // [4][TQ][64] partial O
    const int tid  = threadIdx.x;
    const int warp = tid >> 5, lane = tid & 31;
    const int g = lane >> 2, t = lane & 3;
    const int hbase = h * DH;

    // stage Q tile (raw fp32; used for residual at the end)
    {
        int r = tid >> 4, c = (tid & 15) * 4;
        float4 v = *(const float4*)(Qp + (size_t)(b * NQ + q0 + r) * DD + hbase + c);
        *(float4*)(Qs + r * QP + c) = v;
    }
    __syncthreads();

    const float scale = 0.04419417382415922f;  // 1/sqrt(512)

    // ---- S phase: warp owns 32 toks per 256-tok tile; m16n8k8 tf32 mma ----
    for (int kp = 0; kp < NK; kp += KT) {
        __syncthreads();
        {   // stage K tile (tf32-rounded), stride KPK
            int rr = tid >> 4, c = (tid & 15) * 4;
#pragma unroll
            for (int it = 0; it < KT / 16; it++) {
                int k = it * 16 + rr;
                float4 v = *(const float4*)(Kp + (size_t)(b * NK + kp + k) * DD + hbase + c);
                v.x = f2tf32f(v.x); v.y = f2tf32f(v.y);
                v.z = f2tf32f(v.z); v.w = f2tf32f(v.w);
                *(float4*)(KV + k * KPK + c) = v;
            }
        }
        __syncthreads();

        float c4[4][4];
#pragma unroll
        for (int j = 0; j < 4; j++)
#pragma unroll
            for (int i = 0; i < 4; i++) c4[j][i] = 0.f;

#pragma unroll
        for (int kc = 0; kc < 8; kc++) {
            const int d0 = kc * 8;
            uint32_t a0 = f2tf32(Qs[g * QP + d0 + t]);
            uint32_t a1 = f2tf32(Qs[(g + 8) * QP + d0 + t]);
            uint32_t a2 = f2tf32(Qs[g * QP + d0 + t + 4]);
            uint32_t a3 = f2tf32(Qs[(g + 8) * QP + d0 + t + 4]);
#pragma unroll
            for (int j = 0; j < 4; j++) {
                const int tok0 = warp * 32 + j * 8;
                uint32_t b0 = __float_as_uint(KV[(tok0 + g) * KPK + d0 + t]);
                uint32_t b1 = __float_as_uint(KV[(tok0 + g) * KPK + d0 + t + 4]);
                mma_tf32(c4[j], a0, a1, a2, a3, b0, b1);
            }
        }
#pragma unroll
        for (int j = 0; j < 4; j++) {
            const int col = kp + warp * 32 + j * 8 + 2 * t;
            *(float2*)(Ss + g * SP + col) =
                make_float2(c4[j][0] * scale, c4[j][1] * scale);
            *(float2*)(Ss + (g + 8) * SP + col) =
                make_float2(c4[j][2] * scale, c4[j][3] * scale);
        }
    }
    __syncthreads();

    // ---- softmax per row (warp handles 2 rows), write A (streaming) ----
    {
#pragma unroll
        for (int rr = 0; rr < 2; rr++) {
            int r = warp * 2 + rr;
            float* row = Ss + r * SP;
            float m = -1e30f;
#pragma unroll 4
            for (int k = lane * 4; k < NK; k += 128) {
                float4 v = *(const float4*)(row + k);
                m = fmaxf(m, fmaxf(fmaxf(v.x, v.y), fmaxf(v.z, v.w)));
            }
#pragma unroll
            for (int o = 16; o; o >>= 1) m = fmaxf(m, __shfl_xor_sync(0xffffffffu, m, o));
            float s = 0.f;
#pragma unroll 4
            for (int k = lane * 4; k < NK; k += 128) {
                float4 v = *(const float4*)(row + k);
                v.x = fast_exp(v.x - m); v.y = fast_exp(v.y - m);
                v.z = fast_exp(v.z - m); v.w = fast_exp(v.w - m);
                s += (v.x + v.y) + (v.z + v.w);
                *(float4*)(row + k) = v;
            }
#pragma unroll
            for (int o = 16; o; o >>= 1) s += __shfl_xor_sync(0xffffffffu, s, o);
            float inv = 1.0f / s;
            float* arow = Aout + (size_t)((h * BB + b) * NQ + q0 + r) * NK;
#pragma unroll 4
            for (int k = lane * 4; k < NK; k += 128) {
                float4 v = *(const float4*)(row + k);
                v.x *= inv; v.y *= inv; v.z *= inv; v.w *= inv;
                *(float4*)(row + k) = v;         // normalized, reused by AV
                __stcs((float4*)(arow + k), v);  // streaming A output
            }
        }
    }

    // ---- AV phase (tf32 mma): warp = (phase p over k-chunks, d-half) ----
    {
        const int p = warp >> 1, h2 = warp & 1;
        float c4[4][4];
#pragma unroll
        for (int j = 0; j < 4; j++)
#pragma unroll
            for (int i = 0; i < 4; i++) c4[j][i] = 0.f;

        for (int kp = 0; kp < NK; kp += KT) {
            __syncthreads();
            {   // stage V tile (tf32-rounded), stride KPV
                int rr = tid >> 4, c = (tid & 15) * 4;
#pragma unroll
                for (int it = 0; it < KT / 16; it++) {
                    int k = it * 16 + rr;
                    float4 v = *(const float4*)(Vp + (size_t)(b * NK + kp + k) * DD + hbase + c);
                    v.x = f2tf32f(v.x); v.y = f2tf32f(v.y);
                    v.z = f2tf32f(v.z); v.w = f2tf32f(v.w);
                    *(float4*)(KV + k * KPV + c) = v;
                }
            }
            __syncthreads();

#pragma unroll
            for (int ci = 0; ci < 8; ci++) {
                const int kl0 = (ci * 4 + p) * 8;   // local k-chunk base
                const int kg0 = kp + kl0;
                uint32_t a0 = f2tf32(Ss[g * SP + kg0 + t]);
                uint32_t a1 = f2tf32(Ss[(g + 8) * SP + kg0 + t]);
                uint32_t a2 = f2tf32(Ss[g * SP + kg0 + t + 4]);
                uint32_t a3 = f2tf32(Ss[(g + 8) * SP + kg0 + t + 4]);
#pragma unroll
                for (int j = 0; j < 4; j++) {
                    const int d0 = h2 * 32 + j * 8;
                    uint32_t b0 = __float_as_uint(KV[(kl0 + t) * KPV + d0 + g]);
                    uint32_t b1 = __float_as_uint(KV[(kl0 + t + 4) * KPV + d0 + g]);
                    mma_tf32(c4[j], a0, a1, a2, a3, b0, b1);
                }
            }
        }
#pragma unroll
        for (int j = 0; j < 4; j++) {
            const int d0 = h2 * 32 + j * 8 + 2 * t;
            *(float2*)(Op + (p * TQ + g) * 64 + d0)     = make_float2(c4[j][0], c4[j][1]);
            *(float2*)(Op + (p * TQ + g + 8) * 64 + d0) = make_float2(c4[j][2], c4[j][3]);
        }
    }
    __syncthreads();
    // reduce 4 k-phases, add Q residual, write O1
    for (int idx = tid; idx < TQ * 64; idx += 256) {
        int q = idx >> 6, dd = idx & 63;
        float o = Op[(0 * TQ + q) * 64 + dd] + Op[(1 * TQ + q) * 64 + dd]
                + Op[(2 * TQ + q) * 64 + dd] + Op[(3 * TQ + q) * 64 + dd];
        o += Qs[q * QP + dd];
        O1[(size_t)(b * NQ + q0 + q) * DD + hbase + dd] = o;
    }
}

// ---------------- layernorm over last dim (512), warp per row --------------
__global__ void __launch_bounds__(256) ln_kernel(const float* __restrict__ X,
                                                 const float* __restrict__ g,
                                                 const float* __restrict__ bt,
                                                 float* __restrict__ Y) {
    int row = blockIdx.x * 8 + (threadIdx.x >> 5);
    int lane = threadIdx.x & 31;
    const float* x = X + (size_t)row * 512;
    float4 v[4];
    float s = 0.f, s2 = 0.f;
#pragma unroll
    for (int i = 0; i < 4; i++) {
        v[i] = *(const float4*)(x + lane * 4 + i * 128);
        s  += (v[i].x + v[i].y) + (v[i].z + v[i].w);
        s2 += (v[i].x * v[i].x + v[i].y * v[i].y) + (v[i].z * v[i].z + v[i].w * v[i].w);
    }
#pragma unroll
    for (int o = 16; o; o >>= 1) {
        s  += __shfl_xor_sync(0xffffffffu, s,  o);
        s2 += __shfl_xor_sync(0xffffffffu, s2, o);
    }
    float m   = s * (1.f / 512.f);
    float var = s2 * (1.f / 512.f) - m * m;
    float r   = rsqrtf(var + 1e-5f);
#pragma unroll
    for (int i = 0; i < 4; i++) {
        int c = lane * 4 + i * 128;
        float4 gg = *(const float4*)(g + c);
        float4 bb = *(const float4*)(bt + c);
        float4 o;
        o.x = (v[i].x - m) * r * gg.x + bb.x;
        o.y = (v[i].y - m) * r * gg.y + bb.y;
        o.z = (v[i].z - m) * r * gg.z + bb.z;
        o.w = (v[i].w - m) * r * gg.w + bb.w;
        *(float4*)(Y + (size_t)row * 512 + c) = o;
    }
}

// ---------------------------- launcher -------------------------------------
extern "C" void kernel_launch(void* const* d_in, const int* in_sizes, int n_in,
                              void* d_out, int out_size) {
    const float* Q  = (const float*)d_in[0];
    const float* K  = (const float*)d_in[1];
    const float* Wq = (const float*)d_in[2];
    const float* bq = (const float*)d_in[3];
    const float* Wk = (const float*)d_in[4];
    const float* bk = (const float*)d_in[5];
    const float* Wv = (const float*)d_in[6];
    const float* bv = (const float*)d_in[7];
    const float* Wo = (const float*)d_in[8];
    const float* bo = (const float*)d_in[9];
    const float* g0 = (const float*)d_in[10];
    const float* b0 = (const float*)d_in[11];
    const float* g1 = (const float*)d_in[12];
    const float* b1 = (const float*)d_in[13];

    float* out = (float*)d_out;
    float* Aout = out + ((size_t)out_size - A_ELEMS);  // O first, A second

    float *Qp, *Kp, *Vp, *O1, *X;
    cudaGetSymbolAddress((void**)&Qp, g_Qp);
    cudaGetSymbolAddress((void**)&Kp, g_Kp);
    cudaGetSymbolAddress((void**)&Vp, g_Vp);
    cudaGetSymbolAddress((void**)&O1, g_O1);
    cudaGetSymbolAddress((void**)&X,  g_X);

    cudaFuncSetAttribute(attn_kernel, cudaFuncAttributeMaxDynamicSharedMemorySize,
                         ATTN_SMEM_BYTES);

    dim3 gg(512 / 64, M_ROWS / 128);
    gemm512<false><<<gg, 256>>>(Q, Wq, bq, Qp);
    gemm512_kv<<<gg, 256>>>(K, Wk, bk, Wv, bv, Kp, Vp);

    attn_kernel<<<dim3(NQ / TQ, BB, HH), 256, ATTN_SMEM_BYTES>>>(Qp, Kp, Vp, Aout, O1);

    ln_kernel<<<M_ROWS / 8, 256>>>(O1, g0, b0, X);
    gemm512<true><<<gg, 256>>>(X, Wo, bo, O1);
    ln_kernel<<<M_ROWS / 8, 256>>>(O1, g1, b1, out);
}